// round 14
// baseline (speedup 1.0000x reference)
#include <cuda_runtime.h>
#include <cuda_fp16.h>
#include <cstdint>

#define B_    16
#define N_    3136
#define DIM   512
#define HEADS 8
#define HW    56
#define SD    256
#define S_    32
#define BN    (B_ * N_)
#define ELEMS ((long)BN * DIM)

// ---------------- scratch ----------------
__device__ __half g_x16[ELEMS];          // fp16 x
__device__ __half g_d116[ELEMS];         // fp16 dwconv out
__device__ __half g_a316[ELEMS];         // fp16 attn out
__device__ __half g_q16[ELEMS];          // fp16 q (GEMM out)
__device__ __half g_w16[3][DIM * DIM];   // fp16 weights: q, pw, proj
__device__ float g_half[B_][32][N_];     // 16-ch sums of kv (from GEMM epilogue)
__device__ float g_k[2 * B_ * HEADS * 49 * S_];
__device__ float g_v[2 * B_ * HEADS * 49 * S_];

// ---------------- helpers ----------------
__device__ __forceinline__ uint32_t smem_u32(const void* p) {
    uint32_t a;
    asm("{ .reg .u64 t; cvta.to.shared.u64 t, %1; cvt.u32.u64 %0, t; }" : "=r"(a) : "l"(p));
    return a;
}
__device__ __forceinline__ void cp16(uint32_t d, const void* g) {
    asm volatile("cp.async.cg.shared.global [%0], [%1], 16;" :: "r"(d), "l"(g));
}
#define CP_COMMIT() asm volatile("cp.async.commit_group;" ::: "memory")
#define CP_WAIT(n)  asm volatile("cp.async.wait_group %0;" :: "n"(n) : "memory")

#define LDSM_X4(r, a) \
    asm volatile("ldmatrix.sync.aligned.m8n8.x4.shared.b16 {%0,%1,%2,%3}, [%4];" \
        : "=r"((r)[0]), "=r"((r)[1]), "=r"((r)[2]), "=r"((r)[3]) : "r"(a))
#define LDSM_X2(r, a) \
    asm volatile("ldmatrix.sync.aligned.m8n8.x2.shared.b16 {%0,%1}, [%2];" \
        : "=r"((r)[0]), "=r"((r)[1]) : "r"(a))
#define MMA16816F16(c, a, b) \
    asm volatile("mma.sync.aligned.m16n8k16.row.col.f32.f16.f16.f32 " \
        "{%0,%1,%2,%3},{%4,%5,%6,%7},{%8,%9},{%0,%1,%2,%3};" \
        : "+f"((c)[0]), "+f"((c)[1]), "+f"((c)[2]), "+f"((c)[3]) \
        : "r"((a)[0]), "r"((a)[1]), "r"((a)[2]), "r"((a)[3]), "r"((b)[0]), "r"((b)[1]))

#define FMA2(acc, a, b) \
    asm("fma.rn.f32x2 %0, %1, %2, %0;" : "+l"(acc) : "l"(a), "l"(b))
#define PACK2(d, x, y)  asm("mov.b64 %0, {%1,%2};" : "=l"(d) : "f"(x), "f"(y))
#define UNPACK2(x, y, d) asm("mov.b64 {%0,%1}, %2;" : "=f"(x), "=f"(y) : "l"(d))

__device__ __forceinline__ void store_h4(float4 v, __half* dst) {
    __half2* d = (__half2*)dst;
    d[0] = __floats2half2_rn(v.x, v.y);
    d[1] = __floats2half2_rn(v.z, v.w);
}

// ---------------- weight conversion: 3 matrices in one launch ----------------
__global__ void wsplit3_kernel(const float* __restrict__ s0, const float* __restrict__ s1,
                               const float* __restrict__ s2, __half* __restrict__ out) {
    int w = blockIdx.y;
    const float* src = w == 0 ? s0 : (w == 1 ? s1 : s2);
    long i = (long)blockIdx.x * blockDim.x + threadIdx.x;
    float4 v = ((const float4*)src)[i];
    store_h4(v, out + (long)w * DIM * DIM + i * 4);
}

// ---------------- 3x3 depthwise conv + fused x convert ----------------
__global__ void __launch_bounds__(128)
dwconv_kernel(const float* __restrict__ x, const float* __restrict__ w,
              const float* __restrict__ bias,
              __half* __restrict__ o16, __half* __restrict__ x16) {
    int p0 = blockIdx.x * 8;
    int c4 = threadIdx.x * 4;
    float wr[9][4];
    #pragma unroll
    for (int t = 0; t < 9; t++)
        #pragma unroll
        for (int cc = 0; cc < 4; cc++) wr[t][cc] = w[(c4 + cc) * 9 + t];
    float4 b4 = *(const float4*)(bias + c4);

    #pragma unroll
    for (int pp = 0; pp < 8; pp++) {
        int p = p0 + pp;
        int b = p / N_, pix = p - b * N_;
        int hy = pix / HW, hx = pix - hy * HW;
        float4 acc = b4, xc = make_float4(0.f, 0.f, 0.f, 0.f);
        #pragma unroll
        for (int dy = 0; dy < 3; dy++) {
            int yy = hy + dy - 1;
            if (yy < 0 || yy >= HW) continue;
            #pragma unroll
            for (int dx = 0; dx < 3; dx++) {
                int xx = hx + dx - 1;
                if (xx < 0 || xx >= HW) continue;
                float4 v = *(const float4*)(x + ((long)b * N_ + yy * HW + xx) * DIM + c4);
                if (dy == 1 && dx == 1) xc = v;
                int t = dy * 3 + dx;
                acc.x += wr[t][0] * v.x; acc.y += wr[t][1] * v.y;
                acc.z += wr[t][2] * v.z; acc.w += wr[t][3] * v.w;
            }
        }
        long off = (long)p * DIM + c4;
        store_h4(acc, o16 + off);
        store_h4(xc,  x16 + off);
    }
}

// ---------------------------------------------------------------------------
// fp16 mma.sync GEMM — 3-stage cp.async, one sync per chunk; epilogue modes:
//   mode 0: fp32 C (+bias)   mode 1: fp16 C16   mode 2: 16-ch group sums -> g_half
// ---------------------------------------------------------------------------
#define STAGE_B  20480
#define GSMEM    (3 * STAGE_B)

struct GemmArgs {
    const __half *A, *W;
    const float* bias;
    float* C;
    __half* C16;
    int mode;
};

__global__ void __launch_bounds__(256, 2)
gemm_dual(GemmArgs a0, GemmArgs a1) {
    const GemmArgs& g = blockIdx.z ? a1 : a0;
    const __half* __restrict__ A = g.A;
    const __half* __restrict__ W = g.W;
    const float* bias = g.bias;

    extern __shared__ char smem[];
    uint32_t sb = smem_u32(smem);
    const int tid = threadIdx.x, lane = tid & 31, wid = tid >> 5;
    const int wm = wid & 1, wn = wid >> 1;
    const long m0 = (long)blockIdx.x * 128;
    const int n0 = blockIdx.y * 128;

    auto load_chunk = [&](int ck, int st) {
        uint32_t base = sb + st * STAGE_B;
        #pragma unroll
        for (int it = 0; it < 4; it++) {
            int idx = tid + it * 256;
            int arr = idx >> 9;
            int loc = idx & 511;
            int r = loc >> 2, seg = loc & 3;
            const __half* gp = arr == 0
                ? A + (m0 + r) * DIM + ck * 32 + seg * 8
                : W + (long)(n0 + r) * DIM + ck * 32 + seg * 8;
            cp16(base + arr * 10240 + r * 80 + seg * 16, gp);
        }
        CP_COMMIT();
    };

    float acc[4][4][4];
    #pragma unroll
    for (int i = 0; i < 4; i++)
        #pragma unroll
        for (int j = 0; j < 4; j++)
            #pragma unroll
            for (int r = 0; r < 4; r++) acc[i][j][r] = 0.f;

    load_chunk(0, 0);
    load_chunk(1, 1);

    const int arow = lane & 15;
    const int acolB = (lane >> 4) ? 16 : 0;
    const int brow = lane & 7;
    const int bcolB = ((lane >> 3) & 1) ? 16 : 0;

    for (int c = 0; c < 16; c++) {
        // chunk c must be resident: for c<14 one newer group (c+1) may still fly;
        // for c>=14 drain everything (nothing newer may pend when computing c).
        if (c < 14) { CP_WAIT(1); } else { CP_WAIT(0); }
        __syncthreads();      // all warps see stage c; also fences WAR on stage (c+2)%3
        if (c + 2 < 16) load_chunk(c + 2, (c + 2) % 3);
        uint32_t base = sb + (c % 3) * STAGE_B;
        #pragma unroll
        for (int ks = 0; ks < 2; ks++) {
            const int kb = ks * 32;
            uint32_t ah[4][4];
            #pragma unroll
            for (int i = 0; i < 4; i++) {
                uint32_t addr = base + (wm * 64 + i * 16 + arow) * 80 + kb + acolB;
                LDSM_X4(ah[i], addr);
            }
            #pragma unroll
            for (int j = 0; j < 4; j++) {
                uint32_t baddr = base + 10240 + (wn * 32 + j * 8 + brow) * 80 + kb + bcolB;
                uint32_t wh2[2];
                LDSM_X2(wh2, baddr);
                #pragma unroll
                for (int i = 0; i < 4; i++)
                    MMA16816F16(acc[i][j], ah[i], wh2);
            }
        }
    }

    if (g.mode == 2) {
        // 16-channel group sums -> g_half[b][group][pix]; bias folded in
        #pragma unroll
        for (int i = 0; i < 4; i++) {
            float gA0 = 0.f, gA8 = 0.f, gB0 = 0.f, gB8 = 0.f;
            #pragma unroll
            for (int j = 0; j < 4; j++) {
                int col = n0 + wn * 32 + j * 8 + (lane & 3) * 2;
                float b0 = bias[col], b1 = bias[col + 1];
                float s0 = acc[i][j][0] + b0 + acc[i][j][1] + b1;
                float s8 = acc[i][j][2] + b0 + acc[i][j][3] + b1;
                if (j < 2) { gA0 += s0; gA8 += s8; }
                else       { gB0 += s0; gB8 += s8; }
            }
            #pragma unroll
            for (int d = 1; d <= 2; d <<= 1) {
                gA0 += __shfl_xor_sync(0xffffffffu, gA0, d);
                gA8 += __shfl_xor_sync(0xffffffffu, gA8, d);
                gB0 += __shfl_xor_sync(0xffffffffu, gB0, d);
                gB8 += __shfl_xor_sync(0xffffffffu, gB8, d);
            }
            if ((lane & 3) == 0) {
                int g0 = (n0 + wn * 32) >> 4, g1 = g0 + 1;
                long m = m0 + wm * 64 + i * 16 + (lane >> 2);
                int bb = (int)(m / N_), pix = (int)(m - (long)bb * N_);
                g_half[bb][g0][pix] = gA0;
                g_half[bb][g1][pix] = gB0;
                m += 8; bb = (int)(m / N_); pix = (int)(m - (long)bb * N_);
                g_half[bb][g0][pix] = gA8;
                g_half[bb][g1][pix] = gB8;
            }
        }
    } else if (g.mode == 1) {
        __half* C16 = g.C16;
        #pragma unroll
        for (int i = 0; i < 4; i++) {
            long r0 = m0 + wm * 64 + i * 16 + (lane >> 2);
            #pragma unroll
            for (int j = 0; j < 4; j++) {
                int col = n0 + wn * 32 + j * 8 + (lane & 3) * 2;
                *(__half2*)(C16 + r0 * DIM + col) =
                    __floats2half2_rn(acc[i][j][0], acc[i][j][1]);
                *(__half2*)(C16 + (r0 + 8) * DIM + col) =
                    __floats2half2_rn(acc[i][j][2], acc[i][j][3]);
            }
        }
    } else {
        float* C = g.C;
        #pragma unroll
        for (int i = 0; i < 4; i++) {
            long r0 = m0 + wm * 64 + i * 16 + (lane >> 2);
            #pragma unroll
            for (int j = 0; j < 4; j++) {
                int col = n0 + wn * 32 + j * 8 + (lane & 3) * 2;
                float b0 = bias ? bias[col] : 0.f, b1 = bias ? bias[col + 1] : 0.f;
                float2 v0 = { acc[i][j][0] + b0, acc[i][j][1] + b1 };
                float2 v1 = { acc[i][j][2] + b0, acc[i][j][3] + b1 };
                *(float2*)(C + r0 * DIM + col) = v0;
                *(float2*)(C + (r0 + 8) * DIM + col) = v1;
            }
        }
    }
}

// ---------------- prep ----------------
__global__ void prep_kernel(const float* __restrict__ fc0, const float* __restrict__ fc1,
                            const float* __restrict__ sg0, const float* __restrict__ sg1,
                            const float* __restrict__ lw0, const float* __restrict__ lb0,
                            const float* __restrict__ lw1, const float* __restrict__ lb1) {
    int blk = blockIdx.x;
    int br = blk >> 7, bh = blk & 127, b = bh >> 3, h = bh & 7;
    int tid = threadIdx.x;
    __shared__ float pooled[49][32], tmp[49][32], vsh[49][33];

    for (int idx = tid; idx < 49*32; idx += 256) {
        int w = idx >> 5, s = idx & 31;
        int ky = w / 7, kx = w - ky * 7;
        float sum;
        if (br == 0) {
            int ll0 = 2*s, ll1 = 2*s + 1;
            int p0 = ((ll0>>3)*7 + ky)*HW + (ll0&7)*7 + kx;
            int p1 = ((ll1>>3)*7 + ky)*HW + (ll1&7)*7 + kx;
            sum = (g_half[b][2*h][p0] + g_half[b][2*h+1][p0]
                 + g_half[b][2*h][p1] + g_half[b][2*h+1][p1]) * (1.f/64.f);
        } else {
            int ll = s >> 1;
            int p = ((ll>>2)*13 + ky*2)*HW + (ll&3)*13 + kx*2;
            sum = g_half[b][16 + 2*h + (s&1)][p] * (1.f/16.f);
        }
        pooled[w][s] = sum;
    }
    __syncthreads();
    const float* fc = br ? fc1 : fc0;
    for (int idx = tid; idx < 49*32; idx += 256) {
        int w = idx >> 5, t = idx & 31;
        float sum = 0.f;
        #pragma unroll
        for (int s = 0; s < 32; s++) sum += pooled[w][s] * fc[t*32+s];
        tmp[w][t] = sum;
    }
    __syncthreads();
    const float* sg = br ? sg1 : sg0;
    const float kscale = 0.17677669529663689f;
    for (int idx = tid; idx < 49*64; idx += 256) {
        int w = idx >> 6, j = idx & 63;
        float sum = 0.f;
        #pragma unroll
        for (int t = 0; t < 32; t++) sum += tmp[w][t] * sg[j*32+t];
        if (j < 32) g_k[(long)blk*1568 + w*32 + j] = sum * kscale;
        else        vsh[w][j-32] = sum;
    }
    __syncthreads();
    const float* lw = br ? lw1 : lw0;
    const float* lb = br ? lb1 : lb0;
    for (int idx = tid; idx < 49*32; idx += 256) {
        int w = idx >> 5, s = idx & 31;
        int wy = w / 7, wx = w - wy * 7, ch = h*S_ + s;
        float acc = vsh[w][s] + lb[ch];
        #pragma unroll
        for (int dy = 0; dy < 3; dy++) {
            int yy = wy + dy - 1;
            if (yy < 0 || yy >= 7) continue;
            #pragma unroll
            for (int dx = 0; dx < 3; dx++) {
                int xx = wx + dx - 1;
                if (xx < 0 || xx >= 7) continue;
                acc += lw[ch*9 + dy*3 + dx] * vsh[yy*7+xx][s];
            }
        }
        g_v[(long)blk*1568 + w*32 + s] = acc;
    }
}

// ---------------- attention: fp16 q, packed f32x2 FMA ----------------
__global__ void __launch_bounds__(256)
attn_kernel(const __half* __restrict__ q, __half* __restrict__ a16) {
    int blk = blockIdx.x;
    int br = blk >> 7, bh = blk & 127, b = bh >> 3, h = bh & 7;
    int tid = threadIdx.x;
    __shared__ float ksh[49][32], vsh[49][32], osh[256][33];
    const float* kp = g_k + (long)blk * 1568;
    const float* vp = g_v + (long)blk * 1568;
    for (int idx = tid; idx < 1568; idx += 256) { ((float*)ksh)[idx] = kp[idx]; ((float*)vsh)[idx] = vp[idx]; }
    __syncthreads();

    int n0 = blockIdx.y * 256, n = n0 + tid;
    if (n < N_) {
        const __half* qp = q + ((long)b*N_ + n)*DIM + h*64 + br*32;
        uint64_t q2[16];
        #pragma unroll
        for (int v = 0; v < 4; v++) {
            uint4 t = *(const uint4*)(qp + v*8);
            const __half2* hp = (const __half2*)&t;
            #pragma unroll
            for (int k2 = 0; k2 < 4; k2++) {
                float2 f = __half22float2(hp[k2]);
                PACK2(q2[v*4 + k2], f.x, f.y);
            }
        }
        float p[49], m = -1e30f;
        #pragma unroll
        for (int j = 0; j < 49; j++) {
            uint64_t acc2 = 0;
            #pragma unroll
            for (int d = 0; d < 8; d++) {
                ulonglong2 kk = *(const ulonglong2*)&ksh[j][d*4];
                FMA2(acc2, q2[d*2], kk.x);
                FMA2(acc2, q2[d*2+1], kk.y);
            }
            float lo, hi; UNPACK2(lo, hi, acc2);
            p[j] = lo + hi; m = fmaxf(m, p[j]);
        }
        float sum = 0.f;
        #pragma unroll
        for (int j = 0; j < 49; j++) { p[j] = __expf(p[j] - m); sum += p[j]; }
        float inv = 1.f / sum;
        uint64_t o2[16];
        #pragma unroll
        for (int d = 0; d < 16; d++) o2[d] = 0;
        #pragma unroll
        for (int j = 0; j < 49; j++) {
            uint64_t pj2; PACK2(pj2, p[j], p[j]);
            #pragma unroll
            for (int d = 0; d < 8; d++) {
                ulonglong2 vv = *(const ulonglong2*)&vsh[j][d*4];
                FMA2(o2[d*2], pj2, vv.x);
                FMA2(o2[d*2+1], pj2, vv.y);
            }
        }
        #pragma unroll
        for (int d = 0; d < 16; d++) {
            float lo, hi; UNPACK2(lo, hi, o2[d]);
            osh[tid][d*2]   = lo * inv;
            osh[tid][d*2+1] = hi * inv;
        }
    }
    __syncthreads();
    int off = br * SD + h * S_;
    for (int idx = tid; idx < 256*16; idx += 256) {
        int qq = idx >> 4, dp = (idx & 15) * 2;
        int nn = n0 + qq;
        if (nn < N_) {
            long o = ((long)b*N_ + nn)*DIM + off + dp;
            *(__half2*)(a16 + o) = __floats2half2_rn(osh[qq][dp], osh[qq][dp+1]);
        }
    }
}

// ---------------- launch ----------------
extern "C" void kernel_launch(void* const* d_in, const int* in_sizes, int n_in,
                              void* d_out, int out_size) {
    const float* x       = (const float*)d_in[0];
    const float* q_w     = (const float*)d_in[3];
    const float* kv_dw_w = (const float*)d_in[4];
    const float* kv_dw_b = (const float*)d_in[5];
    const float* kv_pw_w = (const float*)d_in[6];
    const float* kv_pw_b = (const float*)d_in[7];
    const float* fc_w0   = (const float*)d_in[8];
    const float* fc_w1   = (const float*)d_in[9];
    const float* sg_w0   = (const float*)d_in[10];
    const float* sg_w1   = (const float*)d_in[11];
    const float* lw0     = (const float*)d_in[12];
    const float* lb0     = (const float*)d_in[13];
    const float* lw1     = (const float*)d_in[14];
    const float* lb1     = (const float*)d_in[15];
    const float* proj_w  = (const float*)d_in[16];
    const float* proj_b  = (const float*)d_in[17];
    float* out = (float*)d_out;

    __half *x16, *d116, *a316, *q16, *w16;
    cudaGetSymbolAddress((void**)&x16, g_x16);
    cudaGetSymbolAddress((void**)&d116, g_d116);
    cudaGetSymbolAddress((void**)&a316, g_a316);
    cudaGetSymbolAddress((void**)&q16, g_q16);
    cudaGetSymbolAddress((void**)&w16, g_w16);

    cudaFuncSetAttribute(gemm_dual, cudaFuncAttributeMaxDynamicSharedMemorySize, GSMEM);

    wsplit3_kernel<<<dim3(DIM*DIM/4/256, 3), 256>>>(q_w, kv_pw_w, proj_w, w16);
    dwconv_kernel<<<BN/8, 128>>>(x, kv_dw_w, kv_dw_b, d116, x16);

    GemmArgs kvA { d116, w16 + DIM*DIM,   kv_pw_b, nullptr, nullptr, 2 };
    GemmArgs qA  { x16,  w16,             nullptr, nullptr, q16,     1 };
    GemmArgs pA  { a316, w16 + 2*DIM*DIM, proj_b,  out,     nullptr, 0 };

    gemm_dual<<<dim3(BN/128, DIM/128, 2), 256, GSMEM>>>(kvA, qA);
    prep_kernel<<<256, 256>>>(fc_w0, fc_w1, sg_w0, sg_w1, lw0, lb0, lw1, lb1);
    attn_kernel<<<dim3(256, (N_+255)/256), 256>>>(q16, a316);
    gemm_dual<<<dim3(BN/128, DIM/128, 1), 256, GSMEM>>>(pA, pA);
}